// round 6
// baseline (speedup 1.0000x reference)
#include <cuda_runtime.h>
#include <cuda_bf16.h>
#include <mma.h>
#include <cstdint>

using namespace nvcuda;

// Problem constants
#define TBv 16          // T*B
#define Nv  1024
#define Dv  512
#define Hv  8
#define HDv 64
#define Mv  (TBv * Nv)  // 16384 tokens

// Global bf16 hi/lo planes (3xBF16 decomposition: x = hi + lo)
__device__ __nv_bfloat16 gx_hi[(size_t)Mv * Dv], gx_lo[(size_t)Mv * Dv];
__device__ __nv_bfloat16 gw_hi[4 * Dv * Dv],     gw_lo[4 * Dv * Dv];   // q,k,v,o
__device__ __nv_bfloat16 gq_hi[(size_t)Mv * Dv], gq_lo[(size_t)Mv * Dv]; // head-major
__device__ __nv_bfloat16 gk_hi[(size_t)Mv * Dv], gk_lo[(size_t)Mv * Dv];
__device__ __nv_bfloat16 gv_hi[(size_t)Mv * Dv], gv_lo[(size_t)Mv * Dv];
__device__ __nv_bfloat16 gc_hi[(size_t)Mv * Dv], gc_lo[(size_t)Mv * Dv]; // ctx token-major

// ---------------------------------------------------------------------------
// helpers
// ---------------------------------------------------------------------------
__device__ __forceinline__ void split_store4(float4 v,
                                             __nv_bfloat16* __restrict__ hp,
                                             __nv_bfloat16* __restrict__ lp)
{
    __nv_bfloat16 hx = __float2bfloat16_rn(v.x);
    __nv_bfloat16 hy = __float2bfloat16_rn(v.y);
    __nv_bfloat16 hz = __float2bfloat16_rn(v.z);
    __nv_bfloat16 hw = __float2bfloat16_rn(v.w);
    __nv_bfloat16 lx = __float2bfloat16_rn(v.x - __bfloat162float(hx));
    __nv_bfloat16 ly = __float2bfloat16_rn(v.y - __bfloat162float(hy));
    __nv_bfloat16 lz = __float2bfloat16_rn(v.z - __bfloat162float(hz));
    __nv_bfloat16 lw = __float2bfloat16_rn(v.w - __bfloat162float(hw));
    ((__nv_bfloat162*)hp)[0] = __halves2bfloat162(hx, hy);
    ((__nv_bfloat162*)hp)[1] = __halves2bfloat162(hz, hw);
    ((__nv_bfloat162*)lp)[0] = __halves2bfloat162(lx, ly);
    ((__nv_bfloat162*)lp)[1] = __halves2bfloat162(lz, lw);
}

__device__ __forceinline__ void cp16(uint32_t dst, const void* src) {
    asm volatile("cp.async.cg.shared.global [%0], [%1], 16;" :: "r"(dst), "l"(src));
}
__device__ __forceinline__ void cp_commit() {
    asm volatile("cp.async.commit_group;" ::: "memory");
}

using BFragA  = wmma::fragment<wmma::matrix_a, 16, 16, 16, __nv_bfloat16, wmma::row_major>;
using BFragBc = wmma::fragment<wmma::matrix_b, 16, 16, 16, __nv_bfloat16, wmma::col_major>;
using BFragBr = wmma::fragment<wmma::matrix_b, 16, 16, 16, __nv_bfloat16, wmma::row_major>;
using FragC   = wmma::fragment<wmma::accumulator, 16, 16, 16, float>;

// ---------------------------------------------------------------------------
// split kernel: x + 4 weights -> hi/lo bf16 planes
// ---------------------------------------------------------------------------
#define NXf4 (Mv * Dv / 4)      // 2097152
#define NWf4 (Dv * Dv / 4)      // 65536

__global__ __launch_bounds__(256) void split_kernel(
    const float* __restrict__ x,
    const float* __restrict__ wq, const float* __restrict__ wk,
    const float* __restrict__ wv, const float* __restrict__ wo)
{
    int i = blockIdx.x * 256 + threadIdx.x;
    const float* src;
    __nv_bfloat16 *dh, *dl;
    int j;
    if (i < NXf4) {
        src = x; j = i; dh = gx_hi; dl = gx_lo;
    } else {
        int r = i - NXf4;
        if (r >= 4 * NWf4) return;
        int sel = r / NWf4; j = r % NWf4;
        src = (sel == 0) ? wq : (sel == 1) ? wk : (sel == 2) ? wv : wo;
        dh = gw_hi + (size_t)sel * Dv * Dv;
        dl = gw_lo + (size_t)sel * Dv * Dv;
    }
    float4 v = ((const float4*)src)[j];
    split_store4(v, dh + 4 * (size_t)j, dl + 4 * (size_t)j);
}

// ===========================================================================
// GEMM core: C[128x128] = A(hi+lo) . B(hi+lo)^T, K=512, 3-term bf16.
// 256 threads, 8 warps (2m x 4n), warp tile 64x32. K-chunk 32, 2-stage
// cp.async pipeline. smem stage: Ahi|Alo|Bhi|Blo, each 128 x 40 bf16.
// ===========================================================================
#define G_PLE   5120             // plane elems (128*40)
#define G_PLB   10240            // plane bytes
#define G_STAGE 40960            // stage bytes
#define G_BIAS  81920            // bias offset (bytes)
#define GEMM_SMEM (81920 + 512)

__device__ __forceinline__ void gemm_prefetch(
    uint32_t sb, int stage,
    const __nv_bfloat16* __restrict__ Ah, const __nv_bfloat16* __restrict__ Al,
    const __nv_bfloat16* __restrict__ Bh, const __nv_bfloat16* __restrict__ Bl,
    int k0, int t)
{
    const __nv_bfloat16* pl[4] = {Ah, Al, Bh, Bl};
    const uint32_t base = sb + stage * G_STAGE;
#pragma unroll
    for (int p = 0; p < 4; ++p) {
#pragma unroll
        for (int hh = 0; hh < 2; ++hh) {
            const int o = t + 256 * hh;       // 0..511
            const int row = o >> 2;
            const int seg = o & 3;
            cp16(base + p * G_PLB + row * 80 + seg * 16,
                 pl[p] + (size_t)row * Dv + k0 + seg * 8);
        }
    }
}

__device__ __forceinline__ void g_kstep(const char* smc, int stage, int ks,
                                        int wm, int wn, FragC (&acc)[4][2])
{
    const __nv_bfloat16* S  = (const __nv_bfloat16*)(smc + stage * G_STAGE);
    const __nv_bfloat16* Ah = S;
    const __nv_bfloat16* Al = S + G_PLE;
    const __nv_bfloat16* Bh = S + 2 * G_PLE;
    const __nv_bfloat16* Bl = S + 3 * G_PLE;

    BFragA ahi[4], alo[4];
#pragma unroll
    for (int i = 0; i < 4; ++i) {
        wmma::load_matrix_sync(ahi[i], Ah + (wm + 16 * i) * 40 + ks * 16, 40);
        wmma::load_matrix_sync(alo[i], Al + (wm + 16 * i) * 40 + ks * 16, 40);
    }
#pragma unroll
    for (int j = 0; j < 2; ++j) {
        BFragBc bhi, blo;
        wmma::load_matrix_sync(bhi, Bh + (wn + 16 * j) * 40 + ks * 16, 40);
        wmma::load_matrix_sync(blo, Bl + (wn + 16 * j) * 40 + ks * 16, 40);
#pragma unroll
        for (int i = 0; i < 4; ++i) {
            wmma::mma_sync(acc[i][j], ahi[i], bhi, acc[i][j]);
            wmma::mma_sync(acc[i][j], ahi[i], blo, acc[i][j]);
            wmma::mma_sync(acc[i][j], alo[i], bhi, acc[i][j]);
        }
    }
}

__device__ __forceinline__ void gemm_main(
    const __nv_bfloat16* __restrict__ Ah, const __nv_bfloat16* __restrict__ Al,
    const __nv_bfloat16* __restrict__ Bh, const __nv_bfloat16* __restrict__ Bl,
    char* smc, FragC (&acc)[4][2])
{
    const int t = threadIdx.x;
    const int w = t >> 5;
    const int wm = (w & 1) * 64;
    const int wn = (w >> 1) * 32;
    const uint32_t sb = (uint32_t)__cvta_generic_to_shared(smc);

#pragma unroll
    for (int i = 0; i < 4; ++i)
#pragma unroll
        for (int j = 0; j < 2; ++j)
            wmma::fill_fragment(acc[i][j], 0.0f);

    gemm_prefetch(sb, 0, Ah, Al, Bh, Bl, 0, t);
    cp_commit();

    for (int ch = 0; ch < 16; ++ch) {
        if (ch < 15) {
            gemm_prefetch(sb, (ch + 1) & 1, Ah, Al, Bh, Bl, (ch + 1) * 32, t);
            cp_commit();
            asm volatile("cp.async.wait_group 1;" ::: "memory");
        } else {
            asm volatile("cp.async.wait_group 0;" ::: "memory");
        }
        __syncthreads();                 // stage ch data visible
        g_kstep(smc, ch & 1, 0, wm, wn, acc);
        g_kstep(smc, ch & 1, 1, wm, wn, acc);
        __syncthreads();                 // readers done before overwrite
    }
}

// ---------------------------------------------------------------------------
// QKV projection. grid (128, 12). Epilogue writes head-major hi/lo planes.
// ---------------------------------------------------------------------------
__global__ __launch_bounds__(256, 2) void qkv_gemm_p(
    const float* __restrict__ bq, const float* __restrict__ bk,
    const float* __restrict__ bv)
{
    extern __shared__ char smc[];
    const int t = threadIdx.x;
    const int m0   = blockIdx.x * 128;
    const int wsel = blockIdx.y >> 2;
    const int n0   = (blockIdx.y & 3) * 128;

    const float* bias = (wsel == 0) ? bq : (wsel == 1) ? bk : bv;
    __nv_bfloat16* oh = (wsel == 0) ? gq_hi : (wsel == 1) ? gk_hi : gv_hi;
    __nv_bfloat16* ol = (wsel == 0) ? gq_lo : (wsel == 1) ? gk_lo : gv_lo;

    float* biasS = (float*)(smc + G_BIAS);
    if (t < 128) biasS[t] = bias[n0 + t];

    FragC acc[4][2];
    gemm_main(gx_hi + (size_t)m0 * Dv, gx_lo + (size_t)m0 * Dv,
              gw_hi + (size_t)wsel * Dv * Dv + (size_t)n0 * Dv,
              gw_lo + (size_t)wsel * Dv * Dv + (size_t)n0 * Dv,
              smc, acc);

    // Epilogue: frags -> smem fp32, then bias + split + head-major scatter
    float* Cs = (float*)smc;
    const int w = t >> 5;
    const int wm = (w & 1) * 64;
    const int wn = (w >> 1) * 32;
#pragma unroll
    for (int i = 0; i < 4; ++i)
#pragma unroll
        for (int j = 0; j < 2; ++j)
            wmma::store_matrix_sync(&Cs[(wm + 16 * i) * 132 + wn + 16 * j],
                                    acc[i][j], 132, wmma::mem_row_major);
    __syncthreads();

    const int row = t >> 1;
    const int c0  = (t & 1) * 64;
    const int m  = m0 + row;
    const int tb = m >> 10;
    const int n  = m & 1023;
    const int h  = (n0 + c0) >> 6;
    __nv_bfloat16* dh = oh + ((size_t)(tb * Hv + h) * Nv + n) * HDv;
    __nv_bfloat16* dl = ol + ((size_t)(tb * Hv + h) * Nv + n) * HDv;
#pragma unroll
    for (int c = 0; c < 64; c += 4) {
        float4 v = *(float4*)&Cs[row * 132 + c0 + c];
        v.x += biasS[c0 + c + 0];
        v.y += biasS[c0 + c + 1];
        v.z += biasS[c0 + c + 2];
        v.w += biasS[c0 + c + 3];
        split_store4(v, dh + c, dl + c);
    }
}

// ---------------------------------------------------------------------------
// Output projection: out = ctx @ wo^T + bo. grid (128, 4).
// ---------------------------------------------------------------------------
__global__ __launch_bounds__(256, 2) void out_gemm_p(
    const float* __restrict__ bo, float* __restrict__ out)
{
    extern __shared__ char smc[];
    const int t = threadIdx.x;
    const int m0 = blockIdx.x * 128;
    const int n0 = blockIdx.y * 128;

    float* biasS = (float*)(smc + G_BIAS);
    if (t < 128) biasS[t] = bo[n0 + t];

    FragC acc[4][2];
    gemm_main(gc_hi + (size_t)m0 * Dv, gc_lo + (size_t)m0 * Dv,
              gw_hi + (size_t)3 * Dv * Dv + (size_t)n0 * Dv,
              gw_lo + (size_t)3 * Dv * Dv + (size_t)n0 * Dv,
              smc, acc);

    float* Cs = (float*)smc;
    const int w = t >> 5;
    const int wm = (w & 1) * 64;
    const int wn = (w >> 1) * 32;
#pragma unroll
    for (int i = 0; i < 4; ++i)
#pragma unroll
        for (int j = 0; j < 2; ++j)
            wmma::store_matrix_sync(&Cs[(wm + 16 * i) * 132 + wn + 16 * j],
                                    acc[i][j], 132, wmma::mem_row_major);
    __syncthreads();

    const int row = t >> 1;
    const int c0  = (t & 1) * 64;
    const int m = m0 + row;
    float* dst = out + (size_t)m * Dv + n0 + c0;
#pragma unroll
    for (int c = 0; c < 64; c += 4) {
        float4 v = *(float4*)&Cs[row * 132 + c0 + c];
        v.x += biasS[c0 + c + 0];
        v.y += biasS[c0 + c + 1];
        v.z += biasS[c0 + c + 2];
        v.w += biasS[c0 + c + 3];
        *(float4*)(dst + c) = v;
    }
}

// ===========================================================================
// Attention (3xBF16). Block: 128 q-rows of one (tb,h); 256 threads,
// 8 warps (4m x 2n), warp 32x32. K/V tiles (64 keys) cp.async double-buffered.
// smem layout (bytes):
//   Q planes:   [0, 36864)            128x72 bf16 x2
//   KV stages:  [36864, 110592)       2 stages x 4 planes x (64x72 bf16)
//   S fp32:     [110592, 145408)      128x68 f32
//   S planes:   [145408, 182272)      128x72 bf16 x2
//   dsum:       [182272, 183296)      256 f32
// ===========================================================================
#define A_QHI  0
#define A_QLO  18432
#define A_KV   36864
#define A_KVST 36864            // stage stride (bytes)
#define A_PL   9216             // plane stride within stage (bytes)
#define A_SFP  110592
#define A_SHI  145408
#define A_SLO  163840
#define A_DS   182272
#define ATTN_SMEM 183296

__device__ __forceinline__ void kv_prefetch(uint32_t sb, int stage,
                                            size_t hb, int kt, int t)
{
    const __nv_bfloat16* pl[4] = {gk_hi + hb, gk_lo + hb, gv_hi + hb, gv_lo + hb};
    const uint32_t base = sb + A_KV + stage * A_KVST;
#pragma unroll
    for (int p = 0; p < 4; ++p) {
#pragma unroll
        for (int hh = 0; hh < 2; ++hh) {
            const int o = t + 256 * hh;       // 0..511
            const int row = o >> 3;
            const int seg = o & 7;
            cp16(base + p * A_PL + row * 144 + seg * 16,
                 pl[p] + (size_t)(kt * 64 + row) * HDv + seg * 8);
        }
    }
}

__global__ __launch_bounds__(256) void attn_p()
{
    extern __shared__ char smc[];
    const uint32_t sb = (uint32_t)__cvta_generic_to_shared(smc);
    const int t = threadIdx.x;
    const int w = t >> 5;
    const int wm = (w >> 1) * 32;     // q-rows
    const int wn = (w & 1) * 32;      // key cols (S) / hd cols (ctx)
    const int qt  = blockIdx.x;
    const int tbh = blockIdx.y;
    const int qn0 = qt * 128;
    const size_t hb = (size_t)tbh * Nv * HDv;

    // prefetch Q planes + KV tile 0 as group 0
    {
        const __nv_bfloat16* qs[2] = {gq_hi + hb, gq_lo + hb};
#pragma unroll
        for (int p = 0; p < 2; ++p) {
#pragma unroll
            for (int hh = 0; hh < 4; ++hh) {
                const int o = t + 256 * hh;       // 0..1023
                const int row = o >> 3;
                const int seg = o & 7;
                cp16(sb + A_QHI + p * 18432 + row * 144 + seg * 16,
                     qs[p] + (size_t)(qn0 + row) * HDv + seg * 8);
            }
        }
    }
    kv_prefetch(sb, 0, hb, 0, t);
    cp_commit();

    FragC ctx[2][2];
#pragma unroll
    for (int i = 0; i < 2; ++i)
#pragma unroll
        for (int j = 0; j < 2; ++j)
            wmma::fill_fragment(ctx[i][j], 0.0f);
    float dsum = 0.f;

    const __nv_bfloat16* qhi = (const __nv_bfloat16*)(smc + A_QHI);
    const __nv_bfloat16* qlo = (const __nv_bfloat16*)(smc + A_QLO);
    __nv_bfloat16* shi = (__nv_bfloat16*)(smc + A_SHI);
    __nv_bfloat16* slo = (__nv_bfloat16*)(smc + A_SLO);
    float* sfp = (float*)(smc + A_SFP);

    for (int kt = 0; kt < 16; ++kt) {
        if (kt < 15) {
            kv_prefetch(sb, (kt + 1) & 1, hb, kt + 1, t);
            cp_commit();
            asm volatile("cp.async.wait_group 1;" ::: "memory");
        } else {
            asm volatile("cp.async.wait_group 0;" ::: "memory");
        }
        __syncthreads();   // (1) tile kt K/V (and Q) visible

        const __nv_bfloat16* kh = (const __nv_bfloat16*)(smc + A_KV + (kt & 1) * A_KVST);
        const __nv_bfloat16* kl = kh + A_PL / 2;
        const __nv_bfloat16* vh = kh + A_PL;
        const __nv_bfloat16* vl = kh + 3 * A_PL / 2;

        // S = Q K^T (3xBF16)
        FragC sacc[2][2];
#pragma unroll
        for (int i = 0; i < 2; ++i)
#pragma unroll
            for (int j = 0; j < 2; ++j)
                wmma::fill_fragment(sacc[i][j], 0.0f);
#pragma unroll
        for (int ks = 0; ks < 4; ++ks) {
            BFragA fqh[2], fql[2];
#pragma unroll
            for (int i = 0; i < 2; ++i) {
                wmma::load_matrix_sync(fqh[i], qhi + (wm + 16 * i) * 72 + ks * 16, 72);
                wmma::load_matrix_sync(fql[i], qlo + (wm + 16 * i) * 72 + ks * 16, 72);
            }
#pragma unroll
            for (int j = 0; j < 2; ++j) {
                BFragBc fkh, fkl;
                wmma::load_matrix_sync(fkh, kh + (wn + 16 * j) * 72 + ks * 16, 72);
                wmma::load_matrix_sync(fkl, kl + (wn + 16 * j) * 72 + ks * 16, 72);
#pragma unroll
                for (int i = 0; i < 2; ++i) {
                    wmma::mma_sync(sacc[i][j], fqh[i], fkh, sacc[i][j]);
                    wmma::mma_sync(sacc[i][j], fqh[i], fkl, sacc[i][j]);
                    wmma::mma_sync(sacc[i][j], fql[i], fkh, sacc[i][j]);
                }
            }
        }
#pragma unroll
        for (int i = 0; i < 2; ++i)
#pragma unroll
            for (int j = 0; j < 2; ++j)
                wmma::store_matrix_sync(&sfp[(wm + 16 * i) * 68 + wn + 16 * j],
                                        sacc[i][j], 68, wmma::mem_row_major);
        __syncthreads();   // (2) S fp32 staged

        // relu * 0.125, rowsum partial, split hi/lo
        {
            const int row = t >> 1;
            const int c0  = (t & 1) * 32;
#pragma unroll
            for (int u = 0; u < 8; ++u) {
                float4 s = *(const float4*)&sfp[row * 68 + c0 + 4 * u];
                s.x = fmaxf(s.x * 0.125f, 0.f);
                s.y = fmaxf(s.y * 0.125f, 0.f);
                s.z = fmaxf(s.z * 0.125f, 0.f);
                s.w = fmaxf(s.w * 0.125f, 0.f);
                dsum += s.x + s.y + s.z + s.w;
                split_store4(s, shi + row * 72 + c0 + 4 * u,
                                slo + row * 72 + c0 + 4 * u);
            }
        }
        __syncthreads();   // (3) S planes ready

        // ctx += S V (3xBF16)
#pragma unroll
        for (int ks = 0; ks < 4; ++ks) {
            BFragA fsh[2], fsl[2];
#pragma unroll
            for (int i = 0; i < 2; ++i) {
                wmma::load_matrix_sync(fsh[i], shi + (wm + 16 * i) * 72 + ks * 16, 72);
                wmma::load_matrix_sync(fsl[i], slo + (wm + 16 * i) * 72 + ks * 16, 72);
            }
#pragma unroll
            for (int j = 0; j < 2; ++j) {
                BFragBr fvh, fvl;
                wmma::load_matrix_sync(fvh, vh + ks * 16 * 72 + wn + 16 * j, 72);
                wmma::load_matrix_sync(fvl, vl + ks * 16 * 72 + wn + 16 * j, 72);
#pragma unroll
                for (int i = 0; i < 2; ++i) {
                    wmma::mma_sync(ctx[i][j], fsh[i], fvh, ctx[i][j]);
                    wmma::mma_sync(ctx[i][j], fsh[i], fvl, ctx[i][j]);
                    wmma::mma_sync(ctx[i][j], fsl[i], fvh, ctx[i][j]);
                }
            }
        }
        __syncthreads();   // (4) KV stage / S planes free for reuse
    }

    // Epilogue: rowsum reduce, normalize, write ctx hi/lo planes token-major
    ((float*)(smc + A_DS))[t] = dsum;
#pragma unroll
    for (int i = 0; i < 2; ++i)
#pragma unroll
        for (int j = 0; j < 2; ++j)
            wmma::store_matrix_sync(&sfp[(wm + 16 * i) * 68 + wn + 16 * j],
                                    ctx[i][j], 68, wmma::mem_row_major);
    __syncthreads();

    {
        const float* dso = (const float*)(smc + A_DS);
        const int row = t >> 1;
        const int c0  = (t & 1) * 32;
        const float den = dso[2 * row] + dso[2 * row + 1];
        const float inv = 1.f / (den + 1e-6f);
        const int m = (tbh >> 3) * Nv + qn0 + row;
        __nv_bfloat16* dh = gc_hi + (size_t)m * Dv + (tbh & 7) * HDv + c0;
        __nv_bfloat16* dl = gc_lo + (size_t)m * Dv + (tbh & 7) * HDv + c0;
#pragma unroll
        for (int u = 0; u < 8; ++u) {
            float4 v = *(const float4*)&sfp[row * 68 + c0 + 4 * u];
            v.x *= inv; v.y *= inv; v.z *= inv; v.w *= inv;
            split_store4(v, dh + 4 * u, dl + 4 * u);
        }
    }
}

// ---------------------------------------------------------------------------
extern "C" void kernel_launch(void* const* d_in, const int* in_sizes, int n_in,
                              void* d_out, int out_size)
{
    const float* x  = (const float*)d_in[0];
    const float* wq = (const float*)d_in[1];
    const float* bq = (const float*)d_in[2];
    const float* wk = (const float*)d_in[3];
    const float* bk = (const float*)d_in[4];
    const float* wv = (const float*)d_in[5];
    const float* bv = (const float*)d_in[6];
    const float* wo = (const float*)d_in[7];
    const float* bo = (const float*)d_in[8];
    float* out = (float*)d_out;

    cudaFuncSetAttribute(qkv_gemm_p, cudaFuncAttributeMaxDynamicSharedMemorySize,
                         GEMM_SMEM);
    cudaFuncSetAttribute(out_gemm_p, cudaFuncAttributeMaxDynamicSharedMemorySize,
                         GEMM_SMEM);
    cudaFuncSetAttribute(attn_p, cudaFuncAttributeMaxDynamicSharedMemorySize,
                         ATTN_SMEM);

    const int splitBlocks = (NXf4 + 4 * NWf4 + 255) / 256;   // 9216
    split_kernel<<<splitBlocks, 256>>>(x, wq, wk, wv, wo);
    qkv_gemm_p<<<dim3(Mv / 128, 12), 256, GEMM_SMEM>>>(bq, bk, bv);
    attn_p<<<dim3(Nv / 128, TBv * Hv), 256, ATTN_SMEM>>>();
    out_gemm_p<<<dim3(Mv / 128, Dv / 128), 256, GEMM_SMEM>>>(bo, out);
}